// round 4
// baseline (speedup 1.0000x reference)
#include <cuda_runtime.h>
#include <cuda_bf16.h>

#define BB 256
#define LL 1024
#define DD 126
#define TT 128
#define NEGV -10000.0f
#define KOFF 8.0f
#define EXPNK 0.000335462627902512f   // exp(-KOFF)

__device__ int g_perm[BB];

// Rank batches by length (descending, index tie-break). O(n^2) rank, n=256.
__global__ void rank_kernel(const int* __restrict__ x_len) {
    __shared__ int lens[BB];
    int t = threadIdx.x;
    lens[t] = x_len[t];
    __syncthreads();
    int mylen = lens[t];
    int r = 0;
    for (int j = 0; j < BB; ++j) {
        int lj = lens[j];
        if (lj > mylen || (lj == mylen && j < t)) r++;
    }
    g_perm[r] = t;
}

__device__ __forceinline__ __nv_bfloat162 asbf2(unsigned u) {
    return *reinterpret_cast<__nv_bfloat162*>(&u);
}

__global__ __launch_bounds__(TT) void crf_kernel(
    const float* __restrict__ x,
    const float* __restrict__ trans,
    const int*   __restrict__ x_len,
    const int*   __restrict__ tags,
    float*       __restrict__ out)
{
    __shared__ __nv_bfloat162 sh_e[2][TT / 2];  // w = exp(alpha - C) as bf16 pairs, dbl-buffered
    __shared__ float sh_r[2];                   // scalar normalizer for step l (slot l&1)
    __shared__ float sh_red[12];                // 4 warps x {v, em, tr}

    int i = threadIdx.x;
    // Length-balanced batch assignment: bid k and k+148 share an SM (classic LUT).
    int b = g_perm[blockIdx.x < 148 ? blockIdx.x : 403 - blockIdx.x];
    int len = x_len[b];

    if (i < 2) sh_r[i] = 1.f;
    if (i < TT / 2) {
        // w0: only START=126 is exp(0)=1; pair p holds states (2p, 2p+1)
        float lo = (2 * i == DD) ? 1.f : 0.f;
        float hi = (2 * i + 1 == DD) ? 1.f : 0.f;
        sh_e[0][i] = __floats2bfloat162_rn(lo, hi);
    }

    // exp(transitions) row i -> 64 packed bf16x2 j-pair registers
    __nv_bfloat162 m2[64];
    const float* trow = trans + i * TT;
#pragma unroll
    for (int p = 0; p < 64; ++p) {
        m2[p] = __floats2bfloat162_rn(__expf(trow[2 * p]), __expf(trow[2 * p + 1]));
    }
    float eTstop = __expf(trans[127 * TT + i]);   // exp(T[STOP, i])

    // Emission + transition score: parallel over l, strided by 128 threads.
    const int*   tgb = tags + b * LL;
    const float* xb  = x + (size_t)b * LL * DD;
    float em = 0.f, tr = 0.f;
    for (int l = i; l < len; l += TT) {
        int tg = tgb[l];
        em += xb[(size_t)l * DD + tg];
        int prev = (l > 0) ? tgb[l - 1] : DD;      // START
        tr += trans[tg * TT + prev];
        if (l == len - 1) tr += trans[127 * TT + tg];  // STOP <- last
    }

    __syncthreads();

    // ---- forward scan (pure exp-domain: no log/exp on the critical path) ----
    const float* xrow = xb + i;           // x[b, l, i]
    bool isTag = (i < DD);
    // Emission-exp pipeline: Ecur for step l, lgA raw for l+1, lgB raw prefetch l+2
    float Ecur = __expf(isTag ? xrow[0] : NEGV);
    float lgA  = (len > 1 && isTag) ? xrow[DD] : NEGV;
    float C = 0.f;
    float cterm = 0.f;     // -log r_l, added at top of step l
    float laste = 0.f;
    int buf = 0;

    for (int l = 0; l < len; ++l) {
        // prefetch raw logit for l+2 (long LDG latency hidden across step)
        float lgB = ((l + 2) < len && isTag) ? xrow[(size_t)(l + 2) * DD] : NEGV;
        float r = sh_r[l & 1];
        C += cterm;                         // accumulate -log r_l (valid on thread 0)
        float f = Ecur * r;                 // ready before the dot completes

        const uint4* ep = (const uint4*)(sh_e[buf]);
        const __nv_bfloat162 zz = __floats2bfloat162_rn(0.f, 0.f);
        __nv_bfloat162 a0 = zz, a1 = zz, a2 = zz, a3 = zz, a4 = zz, a5 = zz, a6 = zz, a7 = zz;
#pragma unroll
        for (int q = 0; q < 16; q += 2) {
            uint4 v0 = ep[q];
            uint4 v1 = ep[q + 1];
            a0 = __hfma2(m2[4 * q + 0], asbf2(v0.x), a0);
            a1 = __hfma2(m2[4 * q + 1], asbf2(v0.y), a1);
            a2 = __hfma2(m2[4 * q + 2], asbf2(v0.z), a2);
            a3 = __hfma2(m2[4 * q + 3], asbf2(v0.w), a3);
            a4 = __hfma2(m2[4 * q + 4], asbf2(v1.x), a4);
            a5 = __hfma2(m2[4 * q + 5], asbf2(v1.y), a5);
            a6 = __hfma2(m2[4 * q + 6], asbf2(v1.z), a6);
            a7 = __hfma2(m2[4 * q + 7], asbf2(v1.w), a7);
        }
        float2 f0 = __bfloat1622float2(a0);
        float2 f1 = __bfloat1622float2(a1);
        float2 f2 = __bfloat1622float2(a2);
        float2 f3 = __bfloat1622float2(a3);
        float2 f4 = __bfloat1622float2(a4);
        float2 f5 = __bfloat1622float2(a5);
        float2 f6 = __bfloat1622float2(a6);
        float2 f7 = __bfloat1622float2(a7);
        float s = (((f0.x + f0.y) + (f1.x + f1.y)) + ((f2.x + f2.y) + (f3.x + f3.y)))
                + (((f4.x + f4.y) + (f5.x + f5.y)) + ((f6.x + f6.y) + (f7.x + f7.y)));

        float w = s * f;                    // unnormalized-by-r_{l+1} new value
        ((__nv_bfloat16*)sh_e[buf ^ 1])[i] = __float2bfloat16(w);
        if (i == 0) sh_r[(l + 1) & 1] = EXPNK * __frcp_rn(w);  // normalizer for step l+1
        cterm = KOFF + __logf(w);           // -log r_{l+1}; off critical path (MUFU)
        laste = w;
        // rotate emission pipeline (expf off the critical path)
        Ecur = __expf(lgA);
        lgA = lgB;
        buf ^= 1;
        __syncthreads();
    }

    // ---- partition + output ----
    float v = laste * eTstop;     // exp(alpha_i - C) * exp(T[STOP,i])
    float emv = em, trv = tr;
#pragma unroll
    for (int o = 16; o; o >>= 1) {
        v   += __shfl_xor_sync(0xffffffffu, v, o);
        emv += __shfl_xor_sync(0xffffffffu, emv, o);
        trv += __shfl_xor_sync(0xffffffffu, trv, o);
    }
    int w = i >> 5;
    if ((i & 31) == 0) { sh_red[w] = v; sh_red[4 + w] = emv; sh_red[8 + w] = trv; }
    __syncthreads();
    if (i == 0) {
        float S = (sh_red[0] + sh_red[1]) + (sh_red[2] + sh_red[3]);
        float E = (sh_red[4] + sh_red[5]) + (sh_red[6] + sh_red[7]);
        float R = (sh_red[8] + sh_red[9]) + (sh_red[10] + sh_red[11]);
        float partition = C + __logf(S);
        out[b] = R + E - partition;
    }
}

extern "C" void kernel_launch(void* const* d_in, const int* in_sizes, int n_in,
                              void* d_out, int out_size) {
    const float* x     = (const float*)d_in[0];
    const float* trans = (const float*)d_in[1];
    // d_in[2] = x_mask (unused; derived from x_len since mask is a prefix mask)
    const int*   xlen  = (const int*)d_in[3];
    const int*   tags  = (const int*)d_in[4];
    float* out = (float*)d_out;

    rank_kernel<<<1, BB>>>(xlen);
    crf_kernel<<<BB, TT>>>(x, trans, xlen, tags, out);
}

// round 6
// speedup vs baseline: 1.6987x; 1.6987x over previous
#include <cuda_runtime.h>
#include <cuda_bf16.h>

#define BB 256
#define LL 1024
#define DD 126
#define TT 128
#define NEGV -10000.0f
#define NCTA 128
#define LN2 0.6931471805599453

__device__ int g_perm[BB];

// Rank batches by length (descending, index tie-break). O(n^2) rank, n=256.
__global__ void rank_kernel(const int* __restrict__ x_len) {
    __shared__ int lens[BB];
    int t = threadIdx.x;
    lens[t] = x_len[t];
    __syncthreads();
    int mylen = lens[t];
    int r = 0;
    for (int j = 0; j < BB; ++j) {
        int lj = lens[j];
        if (lj > mylen || (lj == mylen && j < t)) r++;
    }
    g_perm[r] = t;
}

__device__ __forceinline__ __nv_bfloat162 asbf2(unsigned u) {
    return *reinterpret_cast<__nv_bfloat162*>(&u);
}

// 128-wide dot: 4 bf16x2 accumulators, chains of 16, fp32 combine.
__device__ __forceinline__ float dot128(const uint4* __restrict__ ep,
                                        const __nv_bfloat162* __restrict__ m2) {
    __nv_bfloat162 zz = __floats2bfloat162_rn(0.f, 0.f);
    __nv_bfloat162 a0 = zz, a1 = zz, a2 = zz, a3 = zz;
#pragma unroll
    for (int q = 0; q < 16; q += 4) {
        uint4 v0 = ep[q], v1 = ep[q + 1], v2 = ep[q + 2], v3 = ep[q + 3];
        a0 = __hfma2(m2[4 * q + 0],  asbf2(v0.x), a0);
        a1 = __hfma2(m2[4 * q + 1],  asbf2(v0.y), a1);
        a2 = __hfma2(m2[4 * q + 2],  asbf2(v0.z), a2);
        a3 = __hfma2(m2[4 * q + 3],  asbf2(v0.w), a3);
        a0 = __hfma2(m2[4 * q + 4],  asbf2(v1.x), a0);
        a1 = __hfma2(m2[4 * q + 5],  asbf2(v1.y), a1);
        a2 = __hfma2(m2[4 * q + 6],  asbf2(v1.z), a2);
        a3 = __hfma2(m2[4 * q + 7],  asbf2(v1.w), a3);
        a0 = __hfma2(m2[4 * q + 8],  asbf2(v2.x), a0);
        a1 = __hfma2(m2[4 * q + 9],  asbf2(v2.y), a1);
        a2 = __hfma2(m2[4 * q + 10], asbf2(v2.z), a2);
        a3 = __hfma2(m2[4 * q + 11], asbf2(v2.w), a3);
        a0 = __hfma2(m2[4 * q + 12], asbf2(v3.x), a0);
        a1 = __hfma2(m2[4 * q + 13], asbf2(v3.y), a1);
        a2 = __hfma2(m2[4 * q + 14], asbf2(v3.z), a2);
        a3 = __hfma2(m2[4 * q + 15], asbf2(v3.w), a3);
    }
    float2 f0 = __bfloat1622float2(a0);
    float2 f1 = __bfloat1622float2(a1);
    float2 f2 = __bfloat1622float2(a2);
    float2 f3 = __bfloat1622float2(a3);
    return ((f0.x + f0.y) + (f1.x + f1.y)) + ((f2.x + f2.y) + (f3.x + f3.y));
}

__global__ __launch_bounds__(TT) void crf_kernel(
    const float* __restrict__ x,
    const float* __restrict__ trans,
    const int*   __restrict__ x_len,
    const int*   __restrict__ tags,
    float*       __restrict__ out)
{
    __shared__ __nv_bfloat162 sh_eA[2][TT / 2];
    __shared__ __nv_bfloat162 sh_eB[2][TT / 2];
    __shared__ float sh_r[2][2];    // [parity][seq]: power-of-2 normalizer, exact
    __shared__ float sh_red[24];    // 4 warps x {vA, emA, trA, vB, emB, trB}

    int i = threadIdx.x;
    int c = blockIdx.x;
    int bA = g_perm[c];          // long sequence
    int bB = g_perm[255 - c];    // short sequence (sorted desc => lenA >= lenB)
    int lenA = x_len[bA];
    int lenB = x_len[bB];

    if (i < 4) ((float*)sh_r)[i] = 1.f;
    if (i < TT / 2) {
        float lo = (2 * i == DD) ? 1.f : 0.f;
        float hi = (2 * i + 1 == DD) ? 1.f : 0.f;
        __nv_bfloat162 v0 = __floats2bfloat162_rn(lo, hi);
        sh_eA[0][i] = v0;
        sh_eB[0][i] = v0;
    }

    // exp(transitions) row i -> 64 packed bf16x2 (shared by both sequences)
    __nv_bfloat162 m2[64];
    const float* trow = trans + i * TT;
#pragma unroll
    for (int p = 0; p < 64; ++p)
        m2[p] = __floats2bfloat162_rn(__expf(trow[2 * p]), __expf(trow[2 * p + 1]));
    float eTstop = __expf(trans[127 * TT + i]);

    // Emission + transition scores for both sequences (parallel over l)
    float emA = 0.f, trA = 0.f, emB = 0.f, trB = 0.f;
    {
        const int*   tg = tags + bA * LL;
        const float* xb = x + (size_t)bA * LL * DD;
        for (int l = i; l < lenA; l += TT) {
            int t = tg[l];
            emA += xb[(size_t)l * DD + t];
            int prev = (l > 0) ? tg[l - 1] : DD;
            trA += trans[t * TT + prev];
            if (l == lenA - 1) trA += trans[127 * TT + t];
        }
        tg = tags + bB * LL;
        xb = x + (size_t)bB * LL * DD;
        for (int l = i; l < lenB; l += TT) {
            int t = tg[l];
            emB += xb[(size_t)l * DD + t];
            int prev = (l > 0) ? tg[l - 1] : DD;
            trB += trans[t * TT + prev];
            if (l == lenB - 1) trB += trans[127 * TT + t];
        }
    }
    __syncthreads();

    bool isTag = (i < DD);
    const float* xrA = x + (size_t)bA * LL * DD + i;
    const float* xrB = x + (size_t)bB * LL * DD + i;

    float EcA = __expf(isTag ? xrA[0] : NEGV);
    float l1A = (lenA > 1 && isTag) ? xrA[DD] : NEGV;
    float EcB = __expf(isTag ? xrB[0] : NEGV);
    float l1B = (lenB > 1 && isTag) ? xrB[DD] : NEGV;
    const float* pA = xrA + 2 * (size_t)DD;   // prefetch cursor (l+2)
    const float* pB = xrB + 2 * (size_t)DD;

    // C accounting (thread 0): add an exponent only when its normalizer is
    // CONSUMED (top of next step), never at publish — the final stored w is
    // un-normalized, so its exponent must not enter C.
    int CiA = 0, CiB = 0;
    int pendA = 0, pendB = 0;
    float lastA = 0.f, lastB = 0.f;
    int buf = 0;
    int l = 0;

    // ---- fused phase: both sequences active ----
    for (; l < lenB; ++l) {
        float l2A = ((l + 2) < lenA && isTag) ? pA[0] : NEGV;
        float l2B = ((l + 2) < lenB && isTag) ? pB[0] : NEGV;
        pA += DD; pB += DD;
        float rA = sh_r[l & 1][0];
        float rB = sh_r[l & 1][1];
        float fA = EcA * rA;
        float fB = EcB * rB;

        float sA = dot128((const uint4*)(sh_eA[buf]), m2);
        float sB = dot128((const uint4*)(sh_eB[buf]), m2);
        float wA = sA * fA;
        float wB = sB * fB;

        ((__nv_bfloat16*)sh_eA[buf ^ 1])[i] = __float2bfloat16(wA);
        ((__nv_bfloat16*)sh_eB[buf ^ 1])[i] = __float2bfloat16(wB);
        if (i == 0) {
            CiA += pendA; CiB += pendB;        // consume previous normalizers
            int exA = (int)(__float_as_uint(wA) >> 23) - 127;
            int exB = (int)(__float_as_uint(wB) >> 23) - 127;
            pendA = exA; pendB = exB;
            sh_r[(l + 1) & 1][0] = __uint_as_float((unsigned)(127 - exA) << 23);
            sh_r[(l + 1) & 1][1] = __uint_as_float((unsigned)(127 - exB) << 23);
        }
        lastA = wA; lastB = wB;
        EcA = __expf(l1A); l1A = l2A;
        EcB = __expf(l1B); l1B = l2B;
        buf ^= 1;
        __syncthreads();
    }

    // ---- tail phase: only the long sequence ----
    for (; l < lenA; ++l) {
        float l2A = ((l + 2) < lenA && isTag) ? pA[0] : NEGV;
        pA += DD;
        float rA = sh_r[l & 1][0];
        float fA = EcA * rA;

        float sA = dot128((const uint4*)(sh_eA[buf]), m2);
        float wA = sA * fA;

        ((__nv_bfloat16*)sh_eA[buf ^ 1])[i] = __float2bfloat16(wA);
        if (i == 0) {
            CiA += pendA;                      // consume previous normalizer
            int exA = (int)(__float_as_uint(wA) >> 23) - 127;
            pendA = exA;
            sh_r[(l + 1) & 1][0] = __uint_as_float((unsigned)(127 - exA) << 23);
        }
        lastA = wA;
        EcA = __expf(l1A); l1A = l2A;
        buf ^= 1;
        __syncthreads();
    }

    // ---- partition + output for both sequences ----
    float vA = lastA * eTstop;
    float vB = lastB * eTstop;
    float e1 = emA, t1 = trA, e2 = emB, t2 = trB;
#pragma unroll
    for (int o = 16; o; o >>= 1) {
        vA += __shfl_xor_sync(0xffffffffu, vA, o);
        e1 += __shfl_xor_sync(0xffffffffu, e1, o);
        t1 += __shfl_xor_sync(0xffffffffu, t1, o);
        vB += __shfl_xor_sync(0xffffffffu, vB, o);
        e2 += __shfl_xor_sync(0xffffffffu, e2, o);
        t2 += __shfl_xor_sync(0xffffffffu, t2, o);
    }
    int w = i >> 5;
    if ((i & 31) == 0) {
        sh_red[w]      = vA; sh_red[4 + w]  = e1; sh_red[8 + w]  = t1;
        sh_red[12 + w] = vB; sh_red[16 + w] = e2; sh_red[20 + w] = t2;
    }
    __syncthreads();
    if (i == 0) {
        float SA = (sh_red[0] + sh_red[1]) + (sh_red[2] + sh_red[3]);
        float EA = (sh_red[4] + sh_red[5]) + (sh_red[6] + sh_red[7]);
        float TA = (sh_red[8] + sh_red[9]) + (sh_red[10] + sh_red[11]);
        float SB = (sh_red[12] + sh_red[13]) + (sh_red[14] + sh_red[15]);
        float EB = (sh_red[16] + sh_red[17]) + (sh_red[18] + sh_red[19]);
        float TB = (sh_red[20] + sh_red[21]) + (sh_red[22] + sh_red[23]);
        float partA = (float)((double)CiA * LN2) + logf(SA);
        float partB = (float)((double)CiB * LN2) + logf(SB);
        out[bA] = TA + EA - partA;
        out[bB] = TB + EB - partB;
    }
}

extern "C" void kernel_launch(void* const* d_in, const int* in_sizes, int n_in,
                              void* d_out, int out_size) {
    const float* x     = (const float*)d_in[0];
    const float* trans = (const float*)d_in[1];
    // d_in[2] = x_mask (unused; prefix mask derived from x_len)
    const int*   xlen  = (const int*)d_in[3];
    const int*   tags  = (const int*)d_in[4];
    float* out = (float*)d_out;

    rank_kernel<<<1, BB>>>(xlen);
    crf_kernel<<<NCTA, TT>>>(x, trans, xlen, tags, out);
}

// round 7
// speedup vs baseline: 1.7621x; 1.0373x over previous
#include <cuda_runtime.h>
#include <cuda_bf16.h>

#define BB 256
#define LL 1024
#define DD 126
#define TT 128
#define NEGV -10000.0f
#define NCTA 128
#define LN2 0.6931471805599453

__device__ int g_perm[BB];

// Rank batches by length (descending, index tie-break). O(n^2) rank, n=256.
__global__ void rank_kernel(const int* __restrict__ x_len) {
    __shared__ int lens[BB];
    int t = threadIdx.x;
    lens[t] = x_len[t];
    __syncthreads();
    int mylen = lens[t];
    int r = 0;
    for (int j = 0; j < BB; ++j) {
        int lj = lens[j];
        if (lj > mylen || (lj == mylen && j < t)) r++;
    }
    g_perm[r] = t;
}

__device__ __forceinline__ __nv_bfloat162 asbf2(unsigned u) {
    return *reinterpret_cast<__nv_bfloat162*>(&u);
}

// 128-wide dot: front-batched loads, 8 bf16x2 accumulators (chains of 8), fp32 combine.
__device__ __forceinline__ float dot128(const uint4* __restrict__ ep,
                                        const __nv_bfloat162* __restrict__ m2) {
    uint4 v[16];
#pragma unroll
    for (int q = 0; q < 16; ++q) v[q] = ep[q];   // all LDS issued before any FMA

    __nv_bfloat162 zz = __floats2bfloat162_rn(0.f, 0.f);
    __nv_bfloat162 a0 = zz, a1 = zz, a2 = zz, a3 = zz, a4 = zz, a5 = zz, a6 = zz, a7 = zz;
#pragma unroll
    for (int q = 0; q < 16; q += 2) {
        a0 = __hfma2(m2[4 * q + 0], asbf2(v[q].x),     a0);
        a1 = __hfma2(m2[4 * q + 1], asbf2(v[q].y),     a1);
        a2 = __hfma2(m2[4 * q + 2], asbf2(v[q].z),     a2);
        a3 = __hfma2(m2[4 * q + 3], asbf2(v[q].w),     a3);
        a4 = __hfma2(m2[4 * q + 4], asbf2(v[q + 1].x), a4);
        a5 = __hfma2(m2[4 * q + 5], asbf2(v[q + 1].y), a5);
        a6 = __hfma2(m2[4 * q + 6], asbf2(v[q + 1].z), a6);
        a7 = __hfma2(m2[4 * q + 7], asbf2(v[q + 1].w), a7);
    }
    float2 f0 = __bfloat1622float2(a0);
    float2 f1 = __bfloat1622float2(a1);
    float2 f2 = __bfloat1622float2(a2);
    float2 f3 = __bfloat1622float2(a3);
    float2 f4 = __bfloat1622float2(a4);
    float2 f5 = __bfloat1622float2(a5);
    float2 f6 = __bfloat1622float2(a6);
    float2 f7 = __bfloat1622float2(a7);
    return (((f0.x + f0.y) + (f1.x + f1.y)) + ((f2.x + f2.y) + (f3.x + f3.y)))
         + (((f4.x + f4.y) + (f5.x + f5.y)) + ((f6.x + f6.y) + (f7.x + f7.y)));
}

__global__ __launch_bounds__(TT, 1) void crf_kernel(
    const float* __restrict__ x,
    const float* __restrict__ trans,
    const int*   __restrict__ x_len,
    const int*   __restrict__ tags,
    float*       __restrict__ out)
{
    __shared__ __nv_bfloat162 sh_eA[2][TT / 2];
    __shared__ __nv_bfloat162 sh_eB[2][TT / 2];
    __shared__ float sh_r[2][2];    // [parity][seq]: power-of-2 normalizer, exact
    __shared__ float sh_red[24];    // 4 warps x {vA, emA, trA, vB, emB, trB}

    int i = threadIdx.x;
    int c = blockIdx.x;
    int bA = g_perm[c];          // long sequence
    int bB = g_perm[255 - c];    // short sequence (sorted desc => lenA >= lenB)
    int lenA = x_len[bA];
    int lenB = x_len[bB];

    if (i < 4) ((float*)sh_r)[i] = 1.f;
    if (i < TT / 2) {
        float lo = (2 * i == DD) ? 1.f : 0.f;
        float hi = (2 * i + 1 == DD) ? 1.f : 0.f;
        __nv_bfloat162 v0 = __floats2bfloat162_rn(lo, hi);
        sh_eA[0][i] = v0;
        sh_eB[0][i] = v0;
    }

    // exp(transitions) row i -> 64 packed bf16x2 (shared by both sequences)
    __nv_bfloat162 m2[64];
    const float* trow = trans + i * TT;
#pragma unroll
    for (int p = 0; p < 64; ++p)
        m2[p] = __floats2bfloat162_rn(__expf(trow[2 * p]), __expf(trow[2 * p + 1]));
    float eTstop = __expf(trans[127 * TT + i]);

    // Emission + transition scores for both sequences (parallel over l)
    float emA = 0.f, trA = 0.f, emB = 0.f, trB = 0.f;
    {
        const int*   tg = tags + bA * LL;
        const float* xb = x + (size_t)bA * LL * DD;
        for (int l = i; l < lenA; l += TT) {
            int t = tg[l];
            emA += xb[(size_t)l * DD + t];
            int prev = (l > 0) ? tg[l - 1] : DD;
            trA += trans[t * TT + prev];
            if (l == lenA - 1) trA += trans[127 * TT + t];
        }
        tg = tags + bB * LL;
        xb = x + (size_t)bB * LL * DD;
        for (int l = i; l < lenB; l += TT) {
            int t = tg[l];
            emB += xb[(size_t)l * DD + t];
            int prev = (l > 0) ? tg[l - 1] : DD;
            trB += trans[t * TT + prev];
            if (l == lenB - 1) trB += trans[127 * TT + t];
        }
    }
    __syncthreads();

    bool isTag = (i < DD);
    const float* xrA = x + (size_t)bA * LL * DD + i;
    const float* xrB = x + (size_t)bB * LL * DD + i;

    // Emission pipeline, prefetch distance 3: Ec (step l), l1 raw (l+1), l2 raw (l+2)
    float EcA = __expf(isTag ? xrA[0] : NEGV);
    float l1A = (lenA > 1 && isTag) ? xrA[DD] : NEGV;
    float l2A = (lenA > 2 && isTag) ? xrA[2 * DD] : NEGV;
    float EcB = __expf(isTag ? xrB[0] : NEGV);
    float l1B = (lenB > 1 && isTag) ? xrB[DD] : NEGV;
    float l2B = (lenB > 2 && isTag) ? xrB[2 * DD] : NEGV;
    const float* pA = xrA + 3 * (size_t)DD;   // prefetch cursor (l+3)
    const float* pB = xrB + 3 * (size_t)DD;

    // C accounting (thread 0): add an exponent only when its normalizer is
    // CONSUMED (top of next step), never at publish.
    int CiA = 0, CiB = 0;
    int pendA = 0, pendB = 0;
    float lastA = 0.f, lastB = 0.f;
    int buf = 0;
    int l = 0;

    // ---- fused phase: both sequences active ----
    for (; l < lenB; ++l) {
        float l3A = ((l + 3) < lenA && isTag) ? pA[0] : NEGV;
        float l3B = ((l + 3) < lenB && isTag) ? pB[0] : NEGV;
        pA += DD; pB += DD;
        float rA = sh_r[l & 1][0];
        float rB = sh_r[l & 1][1];
        float fA = EcA * rA;
        float fB = EcB * rB;

        float sA = dot128((const uint4*)(sh_eA[buf]), m2);
        float sB = dot128((const uint4*)(sh_eB[buf]), m2);
        float wA = sA * fA;
        float wB = sB * fB;

        ((__nv_bfloat16*)sh_eA[buf ^ 1])[i] = __float2bfloat16(wA);
        ((__nv_bfloat16*)sh_eB[buf ^ 1])[i] = __float2bfloat16(wB);
        if (i == 0) {
            CiA += pendA; CiB += pendB;        // consume previous normalizers
            int exA = (int)(__float_as_uint(wA) >> 23) - 127;
            int exB = (int)(__float_as_uint(wB) >> 23) - 127;
            pendA = exA; pendB = exB;
            sh_r[(l + 1) & 1][0] = __uint_as_float((unsigned)(127 - exA) << 23);
            sh_r[(l + 1) & 1][1] = __uint_as_float((unsigned)(127 - exB) << 23);
        }
        lastA = wA; lastB = wB;
        EcA = __expf(l1A); l1A = l2A; l2A = l3A;
        EcB = __expf(l1B); l1B = l2B; l2B = l3B;
        buf ^= 1;
        __syncthreads();
    }

    // ---- tail phase: only the long sequence ----
    for (; l < lenA; ++l) {
        float l3A = ((l + 3) < lenA && isTag) ? pA[0] : NEGV;
        pA += DD;
        float rA = sh_r[l & 1][0];
        float fA = EcA * rA;

        float sA = dot128((const uint4*)(sh_eA[buf]), m2);
        float wA = sA * fA;

        ((__nv_bfloat16*)sh_eA[buf ^ 1])[i] = __float2bfloat16(wA);
        if (i == 0) {
            CiA += pendA;                      // consume previous normalizer
            int exA = (int)(__float_as_uint(wA) >> 23) - 127;
            pendA = exA;
            sh_r[(l + 1) & 1][0] = __uint_as_float((unsigned)(127 - exA) << 23);
        }
        lastA = wA;
        EcA = __expf(l1A); l1A = l2A; l2A = l3A;
        buf ^= 1;
        __syncthreads();
    }

    // ---- partition + output for both sequences ----
    float vA = lastA * eTstop;
    float vB = lastB * eTstop;
    float e1 = emA, t1 = trA, e2 = emB, t2 = trB;
#pragma unroll
    for (int o = 16; o; o >>= 1) {
        vA += __shfl_xor_sync(0xffffffffu, vA, o);
        e1 += __shfl_xor_sync(0xffffffffu, e1, o);
        t1 += __shfl_xor_sync(0xffffffffu, t1, o);
        vB += __shfl_xor_sync(0xffffffffu, vB, o);
        e2 += __shfl_xor_sync(0xffffffffu, e2, o);
        t2 += __shfl_xor_sync(0xffffffffu, t2, o);
    }
    int w = i >> 5;
    if ((i & 31) == 0) {
        sh_red[w]      = vA; sh_red[4 + w]  = e1; sh_red[8 + w]  = t1;
        sh_red[12 + w] = vB; sh_red[16 + w] = e2; sh_red[20 + w] = t2;
    }
    __syncthreads();
    if (i == 0) {
        float SA = (sh_red[0] + sh_red[1]) + (sh_red[2] + sh_red[3]);
        float EA = (sh_red[4] + sh_red[5]) + (sh_red[6] + sh_red[7]);
        float TA = (sh_red[8] + sh_red[9]) + (sh_red[10] + sh_red[11]);
        float SB = (sh_red[12] + sh_red[13]) + (sh_red[14] + sh_red[15]);
        float EB = (sh_red[16] + sh_red[17]) + (sh_red[18] + sh_red[19]);
        float TB = (sh_red[20] + sh_red[21]) + (sh_red[22] + sh_red[23]);
        float partA = (float)((double)CiA * LN2) + logf(SA);
        float partB = (float)((double)CiB * LN2) + logf(SB);
        out[bA] = TA + EA - partA;
        out[bB] = TB + EB - partB;
    }
}

extern "C" void kernel_launch(void* const* d_in, const int* in_sizes, int n_in,
                              void* d_out, int out_size) {
    const float* x     = (const float*)d_in[0];
    const float* trans = (const float*)d_in[1];
    // d_in[2] = x_mask (unused; prefix mask derived from x_len)
    const int*   xlen  = (const int*)d_in[3];
    const int*   tags  = (const int*)d_in[4];
    float* out = (float*)d_out;

    rank_kernel<<<1, BB>>>(xlen);
    crf_kernel<<<NCTA, TT>>>(x, trans, xlen, tags, out);
}